// round 13
// baseline (speedup 1.0000x reference)
#include <cuda_runtime.h>
#include <cuda_fp16.h>

#define N_NODES  100000
#define N_EDGES  2000000
#define N_GRAPHS 1000
#define DIM      32
#define NF       7
#define SLOTS    64   // fixed CSR row stride; P(max degree > 64) ~ 1e-10

// ---- device scratch ----
__device__ __align__(16) unsigned d_hh0[N_NODES * 16];  // fp16 h (2 halfs/unsigned)
__device__ __align__(16) unsigned d_hh1[N_NODES * 16];
__device__ __align__(16) float d_xp[N_NODES * 8];
__device__ __align__(16) float d_pool[N_GRAPHS * DIM];
__device__ int d_cnt[N_NODES];
__device__ __align__(16) int d_csr[N_NODES * SLOTS];

__device__ __forceinline__ float4 fma4(float s, float4 w, float4 a) {
    a.x = fmaf(s, w.x, a.x); a.y = fmaf(s, w.y, a.y);
    a.z = fmaf(s, w.z, a.z); a.w = fmaf(s, w.w, a.w);
    return a;
}
__device__ __forceinline__ float4 add4(float4 a, float4 b) {
    a.x += b.x; a.y += b.y; a.z += b.z; a.w += b.w; return a;
}
__device__ __forceinline__ float4 relu4(float4 a) {
    a.x = fmaxf(a.x, 0.f); a.y = fmaxf(a.y, 0.f);
    a.z = fmaxf(a.z, 0.f); a.w = fmaxf(a.w, 0.f); return a;
}
__device__ __forceinline__ void red_add_v4(float* a, float4 v) {
    asm volatile("red.global.add.v4.f32 [%0], {%1,%2,%3,%4};"
                 :: "l"(a), "f"(v.x), "f"(v.y), "f"(v.z), "f"(v.w)
                 : "memory");
}

// ---- packed f32x2 helpers (bit-identical fp32 SIMD; FFMA2 only via PTX) ----
__device__ __forceinline__ unsigned long long dup2(float s) {
    unsigned long long r;
    asm("mov.b64 %0, {%1, %1};" : "=l"(r) : "f"(s));
    return r;
}
__device__ __forceinline__ unsigned long long fma2(unsigned long long a,
                                                   unsigned long long b,
                                                   unsigned long long c) {
    unsigned long long d;
    asm("fma.rn.f32x2 %0, %1, %2, %3;" : "=l"(d) : "l"(a), "l"(b), "l"(c));
    return d;
}
__device__ __forceinline__ float2 unpk2(unsigned long long v) {
    float2 r;
    asm("mov.b64 {%0, %1}, %2;" : "=f"(r.x), "=f"(r.y) : "l"(v));
    return r;
}

// fp16x4 <-> fp32x4 (packed in uint2)
__device__ __forceinline__ uint2 pack_h4(float4 v) {
    __half2 lo = __floats2half2_rn(v.x, v.y);
    __half2 hi = __floats2half2_rn(v.z, v.w);
    uint2 r;
    r.x = *reinterpret_cast<unsigned*>(&lo);
    r.y = *reinterpret_cast<unsigned*>(&hi);
    return r;
}
__device__ __forceinline__ float4 unpack_h4(uint2 u) {
    __half2 lo = *reinterpret_cast<__half2*>(&u.x);
    __half2 hi = *reinterpret_cast<__half2*>(&u.y);
    float2 a = __half22float2(lo);
    float2 b = __half22float2(hi);
    return make_float4(a.x, a.y, b.x, b.y);
}
__device__ __forceinline__ float4 acc_h4(float4 z, uint2 u) {
    return add4(z, unpack_h4(u));
}

// ---------------------------------------------------------------------------
// zero cnt + pool (must precede build's atomics)
__global__ void zero_k() {
    int i = blockIdx.x * blockDim.x + threadIdx.x;
    if (i < N_NODES) d_cnt[i] = 0;
    if (i < N_GRAPHS * DIM) d_pool[i] = 0.0f;
}

// fused: CSR build (8 edges/thread, 2x int4 index loads) + xp padding
__global__ void build(const int* __restrict__ ei, const float* __restrict__ x) {
    int t = blockIdx.x * blockDim.x + threadIdx.x;   // 800k threads
    if (t < N_EDGES / 8) {
#pragma unroll
        for (int u = 0; u < 2; u++) {
            int4 s4 = ((const int4*)ei)[t * 2 + u];
            int4 dd = ((const int4*)(ei + N_EDGES))[t * 2 + u];
            int p0 = atomicAdd(&d_cnt[dd.x], 1);
            int p1 = atomicAdd(&d_cnt[dd.y], 1);
            int p2 = atomicAdd(&d_cnt[dd.z], 1);
            int p3 = atomicAdd(&d_cnt[dd.w], 1);
            if (p0 < SLOTS) d_csr[dd.x * SLOTS + p0] = s4.x;
            if (p1 < SLOTS) d_csr[dd.y * SLOTS + p1] = s4.y;
            if (p2 < SLOTS) d_csr[dd.z * SLOTS + p2] = s4.z;
            if (p3 < SLOTS) d_csr[dd.w * SLOTS + p3] = s4.w;
        }
    }
    if (t < N_NODES * 8) {
        int n = t >> 3, j = t & 7;
        d_xp[t] = (j < NF) ? x[n * NF + j] : 0.0f;
    }
}

// ---------------------------------------------------------------------------
// Layer 1 fused: 8 lanes per node; lane q owns output dims 4q..4q+3.
__global__ void __launch_bounds__(256)
gin1(const float* __restrict__ W1, const float* __restrict__ b1,
     const float* __restrict__ W2, const float* __restrict__ b2,
     const float* __restrict__ gamma, const float* __restrict__ beta,
     const float* __restrict__ mean, const float* __restrict__ var) {
    __shared__ float4 sW1[NF * 8], sW2[32 * 8];
    __shared__ float4 sB1[8], sB2[8], sSC[8], sSH[8];
    int tid = threadIdx.x;
    if (tid < NF * 8) sW1[tid] = ((const float4*)W1)[tid];
    for (int i = tid; i < 32 * 8; i += 256) sW2[i] = ((const float4*)W2)[i];
    if (tid < 32) {
        if (tid < 8) {
            sB1[tid] = ((const float4*)b1)[tid];
            sB2[tid] = ((const float4*)b2)[tid];
        }
        float sc = gamma[tid] * rsqrtf(var[tid] + 1e-5f);
        float sh = beta[tid] - mean[tid] * sc;
        ((float*)sSC)[tid] = sc;
        ((float*)sSH)[tid] = sh;
    }
    __syncthreads();

    int q = tid & 7;
    int n = (blockIdx.x * 256 + tid) >> 3;   // exact: 3125*32 = 100000

    int deg = d_cnt[n]; if (deg > SLOTS) deg = SLOTS;
    const int* row = d_csr + n * SLOTS;
    float zq = d_xp[n * 8 + q];
    float zb = 0.0f;
    int i = 0;
    for (; i + 2 <= deg; i += 2) {
        int s0 = row[i], s1 = row[i + 1];
        zq += d_xp[s0 * 8 + q];
        zb += d_xp[s1 * 8 + q];
    }
    if (i < deg) zq += d_xp[row[i] * 8 + q];
    zq += zb;

    float4 acc = sB1[q];
#pragma unroll
    for (int k = 0; k < NF; k++) {
        float zk = __shfl_sync(0xffffffffu, zq, k, 8);
        acc = fma4(zk, sW1[k * 8 + q], acc);
    }
    acc = relu4(acc);

    float4 o = sB2[q];
#pragma unroll
    for (int kg = 0; kg < 8; kg++) {
        float ax = __shfl_sync(0xffffffffu, acc.x, kg, 8);
        float ay = __shfl_sync(0xffffffffu, acc.y, kg, 8);
        float az = __shfl_sync(0xffffffffu, acc.z, kg, 8);
        float aw = __shfl_sync(0xffffffffu, acc.w, kg, 8);
        o = fma4(ax, sW2[(kg * 4 + 0) * 8 + q], o);
        o = fma4(ay, sW2[(kg * 4 + 1) * 8 + q], o);
        o = fma4(az, sW2[(kg * 4 + 2) * 8 + q], o);
        o = fma4(aw, sW2[(kg * 4 + 3) * 8 + q], o);
    }
    o = relu4(o);

    float4 sc = sSC[q], sh = sSH[q];
    float4 r;
    r.x = fmaf(o.x, sc.x, sh.x); r.y = fmaf(o.y, sc.y, sh.y);
    r.z = fmaf(o.z, sc.z, sh.z); r.w = fmaf(o.w, sc.w, sh.w);
    ((uint2*)d_hh0)[n * 8 + q] = pack_h4(r);
}

// Gather one node's aggregated z (fp32) — 8 loads in flight, 4 accumulators.
__device__ __forceinline__ float4 gather_node(const uint2* __restrict__ hin,
                                              int n, int q) {
    int deg = d_cnt[n]; if (deg > SLOTS) deg = SLOTS;
    const int4* row4 = reinterpret_cast<const int4*>(d_csr + n * SLOTS);

    float4 z0 = unpack_h4(hin[n * 8 + q]);
    float4 z1 = make_float4(0.f, 0.f, 0.f, 0.f);
    float4 z2 = make_float4(0.f, 0.f, 0.f, 0.f);
    float4 z3 = make_float4(0.f, 0.f, 0.f, 0.f);

    int i = 0;
    for (; i + 8 <= deg; i += 8) {
        int4 ia = row4[i >> 2];
        int4 ib = row4[(i >> 2) + 1];
        uint2 u0 = hin[ia.x * 8 + q];
        uint2 u1 = hin[ia.y * 8 + q];
        uint2 u2 = hin[ia.z * 8 + q];
        uint2 u3 = hin[ia.w * 8 + q];
        uint2 u4 = hin[ib.x * 8 + q];
        uint2 u5 = hin[ib.y * 8 + q];
        uint2 u6 = hin[ib.z * 8 + q];
        uint2 u7 = hin[ib.w * 8 + q];
        z0 = acc_h4(z0, u0); z1 = acc_h4(z1, u1);
        z2 = acc_h4(z2, u2); z3 = acc_h4(z3, u3);
        z0 = acc_h4(z0, u4); z1 = acc_h4(z1, u5);
        z2 = acc_h4(z2, u6); z3 = acc_h4(z3, u7);
    }
    if (i + 4 <= deg) {
        int4 ia = row4[i >> 2];
        uint2 u0 = hin[ia.x * 8 + q];
        uint2 u1 = hin[ia.y * 8 + q];
        uint2 u2 = hin[ia.z * 8 + q];
        uint2 u3 = hin[ia.w * 8 + q];
        z0 = acc_h4(z0, u0); z1 = acc_h4(z1, u1);
        z2 = acc_h4(z2, u2); z3 = acc_h4(z3, u3);
        i += 4;
    }
    const int* row = reinterpret_cast<const int*>(row4);
    for (; i < deg; i++) z0 = acc_h4(z0, hin[row[i] * 8 + q]);

    return add4(add4(z0, z1), add4(z2, z3));
}

// Layers 2..5: fp16 in, fp32 math. TWO nodes per thread; GEMVs use packed
// fma.rn.f32x2 (halves FMA-pipe instructions, bit-identical results).
// NOTE: min-blocks=4 (natural ~59 regs). Forcing 5 causes spills (R11: +21us).
template <int POOL>
__global__ void __launch_bounds__(256, 4)
gin_layer(const uint2* __restrict__ hin, uint2* __restrict__ hout,
          const int* __restrict__ batch,
          const float* __restrict__ W1, const float* __restrict__ b1,
          const float* __restrict__ W2, const float* __restrict__ b2,
          const float* __restrict__ gamma, const float* __restrict__ beta,
          const float* __restrict__ mean, const float* __restrict__ var) {
    __shared__ ulonglong2 sW1[32 * 8], sW2[32 * 8];   // weights as f32x2 pairs
    __shared__ ulonglong2 sB1[8], sB2[8];
    __shared__ float4 sSC[8], sSH[8];
    int tid = threadIdx.x;
    for (int i = tid; i < 32 * 8; i += 256) {
        sW1[i] = ((const ulonglong2*)W1)[i];
        sW2[i] = ((const ulonglong2*)W2)[i];
    }
    if (tid < 32) {
        if (tid < 8) {
            sB1[tid] = ((const ulonglong2*)b1)[tid];
            sB2[tid] = ((const ulonglong2*)b2)[tid];
        }
        float sc = gamma[tid] * rsqrtf(var[tid] + 1e-5f);
        float sh = beta[tid] - mean[tid] * sc;
        ((float*)sSC)[tid] = sc;
        ((float*)sSH)[tid] = sh;
    }
    __syncthreads();

    int q = tid & 7;
    int grp = (blockIdx.x * 256 + tid) >> 3;   // 8-lane group id
    int nA = grp * 2;
    if (nA >= N_NODES) return;
    int nB = nA + 1;   // N_NODES even

    float4 zA = gather_node(hin, nA, q);
    float4 zB = gather_node(hin, nB, q);

    // GEMV1 (packed f32x2, weight LDS shared by both nodes)
    ulonglong2 b1v = sB1[q];
    unsigned long long aA01 = b1v.x, aA23 = b1v.y;
    unsigned long long aB01 = b1v.x, aB23 = b1v.y;
#pragma unroll
    for (int kg = 0; kg < 8; kg++) {
        ulonglong2 w0 = sW1[(kg * 4 + 0) * 8 + q];
        ulonglong2 w1 = sW1[(kg * 4 + 1) * 8 + q];
        ulonglong2 w2 = sW1[(kg * 4 + 2) * 8 + q];
        ulonglong2 w3 = sW1[(kg * 4 + 3) * 8 + q];
        unsigned long long sx = dup2(__shfl_sync(0xffffffffu, zA.x, kg, 8));
        unsigned long long sy = dup2(__shfl_sync(0xffffffffu, zA.y, kg, 8));
        unsigned long long sz = dup2(__shfl_sync(0xffffffffu, zA.z, kg, 8));
        unsigned long long sw = dup2(__shfl_sync(0xffffffffu, zA.w, kg, 8));
        aA01 = fma2(sx, w0.x, aA01); aA23 = fma2(sx, w0.y, aA23);
        aA01 = fma2(sy, w1.x, aA01); aA23 = fma2(sy, w1.y, aA23);
        aA01 = fma2(sz, w2.x, aA01); aA23 = fma2(sz, w2.y, aA23);
        aA01 = fma2(sw, w3.x, aA01); aA23 = fma2(sw, w3.y, aA23);
        unsigned long long tx = dup2(__shfl_sync(0xffffffffu, zB.x, kg, 8));
        unsigned long long ty = dup2(__shfl_sync(0xffffffffu, zB.y, kg, 8));
        unsigned long long tz = dup2(__shfl_sync(0xffffffffu, zB.z, kg, 8));
        unsigned long long tw = dup2(__shfl_sync(0xffffffffu, zB.w, kg, 8));
        aB01 = fma2(tx, w0.x, aB01); aB23 = fma2(tx, w0.y, aB23);
        aB01 = fma2(ty, w1.x, aB01); aB23 = fma2(ty, w1.y, aB23);
        aB01 = fma2(tz, w2.x, aB01); aB23 = fma2(tz, w2.y, aB23);
        aB01 = fma2(tw, w3.x, aB01); aB23 = fma2(tw, w3.y, aB23);
    }
    float2 aA0 = unpk2(aA01), aA1 = unpk2(aA23);
    float2 aB0 = unpk2(aB01), aB1 = unpk2(aB23);
    float4 aAf = make_float4(fmaxf(aA0.x, 0.f), fmaxf(aA0.y, 0.f),
                             fmaxf(aA1.x, 0.f), fmaxf(aA1.y, 0.f));
    float4 aBf = make_float4(fmaxf(aB0.x, 0.f), fmaxf(aB0.y, 0.f),
                             fmaxf(aB1.x, 0.f), fmaxf(aB1.y, 0.f));

    // GEMV2 (packed f32x2)
    ulonglong2 b2v = sB2[q];
    unsigned long long oA01 = b2v.x, oA23 = b2v.y;
    unsigned long long oB01 = b2v.x, oB23 = b2v.y;
#pragma unroll
    for (int kg = 0; kg < 8; kg++) {
        ulonglong2 w0 = sW2[(kg * 4 + 0) * 8 + q];
        ulonglong2 w1 = sW2[(kg * 4 + 1) * 8 + q];
        ulonglong2 w2 = sW2[(kg * 4 + 2) * 8 + q];
        ulonglong2 w3 = sW2[(kg * 4 + 3) * 8 + q];
        unsigned long long sx = dup2(__shfl_sync(0xffffffffu, aAf.x, kg, 8));
        unsigned long long sy = dup2(__shfl_sync(0xffffffffu, aAf.y, kg, 8));
        unsigned long long sz = dup2(__shfl_sync(0xffffffffu, aAf.z, kg, 8));
        unsigned long long sw = dup2(__shfl_sync(0xffffffffu, aAf.w, kg, 8));
        oA01 = fma2(sx, w0.x, oA01); oA23 = fma2(sx, w0.y, oA23);
        oA01 = fma2(sy, w1.x, oA01); oA23 = fma2(sy, w1.y, oA23);
        oA01 = fma2(sz, w2.x, oA01); oA23 = fma2(sz, w2.y, oA23);
        oA01 = fma2(sw, w3.x, oA01); oA23 = fma2(sw, w3.y, oA23);
        unsigned long long tx = dup2(__shfl_sync(0xffffffffu, aBf.x, kg, 8));
        unsigned long long ty = dup2(__shfl_sync(0xffffffffu, aBf.y, kg, 8));
        unsigned long long tz = dup2(__shfl_sync(0xffffffffu, aBf.z, kg, 8));
        unsigned long long tw = dup2(__shfl_sync(0xffffffffu, aBf.w, kg, 8));
        oB01 = fma2(tx, w0.x, oB01); oB23 = fma2(tx, w0.y, oB23);
        oB01 = fma2(ty, w1.x, oB01); oB23 = fma2(ty, w1.y, oB23);
        oB01 = fma2(tz, w2.x, oB01); oB23 = fma2(tz, w2.y, oB23);
        oB01 = fma2(tw, w3.x, oB01); oB23 = fma2(tw, w3.y, oB23);
    }
    float2 oA0 = unpk2(oA01), oA1 = unpk2(oA23);
    float2 oB0 = unpk2(oB01), oB1 = unpk2(oB23);
    float4 oAf = make_float4(fmaxf(oA0.x, 0.f), fmaxf(oA0.y, 0.f),
                             fmaxf(oA1.x, 0.f), fmaxf(oA1.y, 0.f));
    float4 oBf = make_float4(fmaxf(oB0.x, 0.f), fmaxf(oB0.y, 0.f),
                             fmaxf(oB1.x, 0.f), fmaxf(oB1.y, 0.f));

    float4 sc = sSC[q], sh = sSH[q];
    float4 rA, rB;
    rA.x = fmaf(oAf.x, sc.x, sh.x); rA.y = fmaf(oAf.y, sc.y, sh.y);
    rA.z = fmaf(oAf.z, sc.z, sh.z); rA.w = fmaf(oAf.w, sc.w, sh.w);
    rB.x = fmaf(oBf.x, sc.x, sh.x); rB.y = fmaf(oBf.y, sc.y, sh.y);
    rB.z = fmaf(oBf.z, sc.z, sh.z); rB.w = fmaf(oBf.w, sc.w, sh.w);

    if (POOL) {
        red_add_v4(&d_pool[batch[nA] * DIM + q * 4], rA);
        red_add_v4(&d_pool[batch[nB] * DIM + q * 4], rB);
    } else {
        hout[nA * 8 + q] = pack_h4(rA);
        hout[nB * 8 + q] = pack_h4(rB);
    }
}

// head: fc1 + relu + fc2 + log_softmax; one warp per graph
__global__ void head(const float* __restrict__ fc1W, const float* __restrict__ fc1b,
                     const float* __restrict__ fc2W, const float* __restrict__ fc2b,
                     float* __restrict__ out) {
    __shared__ float W1s[32 * 32], W2s[64], b1s[32], b2s[2];
    int tid = threadIdx.x;
    for (int i = tid; i < 32 * 32; i += blockDim.x) W1s[i] = fc1W[i];
    if (tid < 64) W2s[tid] = fc2W[tid];
    if (tid < 32) b1s[tid] = fc1b[tid];
    if (tid < 2)  b2s[tid] = fc2b[tid];
    __syncthreads();

    int warp = tid >> 5, j = tid & 31;
    int g = blockIdx.x * (blockDim.x >> 5) + warp;
    if (g >= N_GRAPHS) return;

    float gj = d_pool[g * DIM + j];
    float a = b1s[j];
#pragma unroll
    for (int k = 0; k < 32; k++)
        a = fmaf(__shfl_sync(0xffffffffu, gj, k), W1s[k * 32 + j], a);
    a = fmaxf(a, 0.0f);

    float p0 = a * W2s[j * 2 + 0];
    float p1 = a * W2s[j * 2 + 1];
#pragma unroll
    for (int off = 16; off > 0; off >>= 1) {
        p0 += __shfl_down_sync(0xffffffffu, p0, off);
        p1 += __shfl_down_sync(0xffffffffu, p1, off);
    }
    if (j == 0) {
        float z0 = p0 + b2s[0];
        float z1 = p1 + b2s[1];
        float m = fmaxf(z0, z1);
        float lse = m + logf(expf(z0 - m) + expf(z1 - m));
        out[g * 2 + 0] = z0 - lse;
        out[g * 2 + 1] = z1 - lse;
    }
}

// ---------------------------------------------------------------------------
extern "C" void kernel_launch(void* const* d_in, const int* in_sizes, int n_in,
                              void* d_out, int out_size) {
    const float* x        = (const float*)d_in[0];
    const int*   ei       = (const int*)d_in[1];
    const int*   batch    = (const int*)d_in[2];
    const float* conv1_W1 = (const float*)d_in[3];
    const float* conv1_b1 = (const float*)d_in[4];
    const float* conv1_W2 = (const float*)d_in[5];
    const float* conv1_b2 = (const float*)d_in[6];
    const float* convs_W1 = (const float*)d_in[7];
    const float* convs_b1 = (const float*)d_in[8];
    const float* convs_W2 = (const float*)d_in[9];
    const float* convs_b2 = (const float*)d_in[10];
    const float* bn_gamma = (const float*)d_in[11];
    const float* bn_beta  = (const float*)d_in[12];
    const float* bn_mean  = (const float*)d_in[13];
    const float* bn_var   = (const float*)d_in[14];
    const float* fc1_W    = (const float*)d_in[15];
    const float* fc1_b    = (const float*)d_in[16];
    const float* fc2_W    = (const float*)d_in[17];
    const float* fc2_b    = (const float*)d_in[18];
    float* out = (float*)d_out;

    zero_k<<<(N_NODES + 255) / 256, 256>>>();
    build<<<(N_NODES * 8 + 255) / 256, 256>>>(ei, x);

    unsigned* hA = nullptr; unsigned* hB = nullptr;
    cudaGetSymbolAddress((void**)&hA, d_hh0);
    cudaGetSymbolAddress((void**)&hB, d_hh1);

    const int NBLK1 = N_NODES * 8 / 256;            // 3125, exact (gin1)
    const int NBLK2 = (N_NODES * 4 + 255) / 256;    // 1563 (2 nodes/thread)

    // layer 1: xp (fp32) -> hh0 (fp16)
    gin1<<<NBLK1, 256>>>(conv1_W1, conv1_b1, conv1_W2, conv1_b2,
                         bn_gamma, bn_beta, bn_mean, bn_var);

    // layers 2..4: ping-pong hh0 -> hh1 -> hh0 -> hh1
    for (int i = 0; i < 3; i++) {
        const uint2* hin = (const uint2*)((i % 2 == 0) ? hA : hB);
        uint2* hout      = (uint2*)((i % 2 == 0) ? hB : hA);
        gin_layer<0><<<NBLK2, 256>>>(hin, hout, batch,
                                     convs_W1 + i * 32 * 32, convs_b1 + i * 32,
                                     convs_W2 + i * 32 * 32, convs_b2 + i * 32,
                                     bn_gamma + (i + 1) * 32, bn_beta + (i + 1) * 32,
                                     bn_mean + (i + 1) * 32,  bn_var + (i + 1) * 32);
    }

    // layer 5 (i=3): input hh1, output pooled (fp32) directly into d_pool
    gin_layer<1><<<NBLK2, 256>>>((const uint2*)hB, nullptr, batch,
                                 convs_W1 + 3 * 32 * 32, convs_b1 + 3 * 32,
                                 convs_W2 + 3 * 32 * 32, convs_b2 + 3 * 32,
                                 bn_gamma + 4 * 32, bn_beta + 4 * 32,
                                 bn_mean + 4 * 32,  bn_var + 4 * 32);

    head<<<(N_GRAPHS + 7) / 8, 256>>>(fc1_W, fc1_b, fc2_W, fc2_b, out);
}

// round 14
// speedup vs baseline: 1.0183x; 1.0183x over previous
#include <cuda_runtime.h>
#include <cuda_fp16.h>

#define N_NODES  100000
#define N_EDGES  2000000
#define N_GRAPHS 1000
#define DIM      32
#define NF       7
#define SLOTS    64   // fixed CSR row stride; P(max degree > 64) ~ 1e-10

// ---- device scratch ----
__device__ __align__(16) unsigned d_hh0[N_NODES * 16];  // fp16 h (2 halfs/unsigned)
__device__ __align__(16) unsigned d_hh1[N_NODES * 16];
__device__ __align__(16) float d_xp[N_NODES * 8];
__device__ __align__(16) float d_pool[N_GRAPHS * DIM];
__device__ int d_cnt[N_NODES];
__device__ __align__(16) int d_csr[N_NODES * SLOTS];

__device__ __forceinline__ float4 fma4(float s, float4 w, float4 a) {
    a.x = fmaf(s, w.x, a.x); a.y = fmaf(s, w.y, a.y);
    a.z = fmaf(s, w.z, a.z); a.w = fmaf(s, w.w, a.w);
    return a;
}
__device__ __forceinline__ float4 add4(float4 a, float4 b) {
    a.x += b.x; a.y += b.y; a.z += b.z; a.w += b.w; return a;
}
__device__ __forceinline__ float4 relu4(float4 a) {
    a.x = fmaxf(a.x, 0.f); a.y = fmaxf(a.y, 0.f);
    a.z = fmaxf(a.z, 0.f); a.w = fmaxf(a.w, 0.f); return a;
}
__device__ __forceinline__ void red_add_v4(float* a, float4 v) {
    asm volatile("red.global.add.v4.f32 [%0], {%1,%2,%3,%4};"
                 :: "l"(a), "f"(v.x), "f"(v.y), "f"(v.z), "f"(v.w)
                 : "memory");
}

// ---- packed f32x2 helpers (bit-identical fp32 SIMD; FFMA2 only via PTX) ----
__device__ __forceinline__ unsigned long long dup2(float s) {
    unsigned long long r;
    asm("mov.b64 %0, {%1, %1};" : "=l"(r) : "f"(s));
    return r;
}
__device__ __forceinline__ unsigned long long fma2(unsigned long long a,
                                                   unsigned long long b,
                                                   unsigned long long c) {
    unsigned long long d;
    asm("fma.rn.f32x2 %0, %1, %2, %3;" : "=l"(d) : "l"(a), "l"(b), "l"(c));
    return d;
}
__device__ __forceinline__ float2 unpk2(unsigned long long v) {
    float2 r;
    asm("mov.b64 {%0, %1}, %2;" : "=f"(r.x), "=f"(r.y) : "l"(v));
    return r;
}

// fp16x4 <-> fp32x4 (packed in uint2)
__device__ __forceinline__ uint2 pack_h4(float4 v) {
    __half2 lo = __floats2half2_rn(v.x, v.y);
    __half2 hi = __floats2half2_rn(v.z, v.w);
    uint2 r;
    r.x = *reinterpret_cast<unsigned*>(&lo);
    r.y = *reinterpret_cast<unsigned*>(&hi);
    return r;
}
__device__ __forceinline__ float4 unpack_h4(uint2 u) {
    __half2 lo = *reinterpret_cast<__half2*>(&u.x);
    __half2 hi = *reinterpret_cast<__half2*>(&u.y);
    float2 a = __half22float2(lo);
    float2 b = __half22float2(hi);
    return make_float4(a.x, a.y, b.x, b.y);
}
__device__ __forceinline__ float4 acc_h4(float4 z, uint2 u) {
    return add4(z, unpack_h4(u));
}
// fp16 pairwise add of two packed rows (one extra fp16 rounding per value)
__device__ __forceinline__ uint2 hadd_u2(uint2 a, uint2 b) {
    __half2 ax = *reinterpret_cast<__half2*>(&a.x);
    __half2 bx = *reinterpret_cast<__half2*>(&b.x);
    __half2 ay = *reinterpret_cast<__half2*>(&a.y);
    __half2 by = *reinterpret_cast<__half2*>(&b.y);
    __half2 rx = __hadd2(ax, bx);
    __half2 ry = __hadd2(ay, by);
    uint2 r;
    r.x = *reinterpret_cast<unsigned*>(&rx);
    r.y = *reinterpret_cast<unsigned*>(&ry);
    return r;
}

// ---------------------------------------------------------------------------
// zero cnt + pool (must precede build's atomics)
__global__ void zero_k() {
    int i = blockIdx.x * blockDim.x + threadIdx.x;
    if (i < N_NODES) d_cnt[i] = 0;
    if (i < N_GRAPHS * DIM) d_pool[i] = 0.0f;
}

// fused: CSR build (8 edges/thread, 2x int4 index loads) + xp padding
__global__ void build(const int* __restrict__ ei, const float* __restrict__ x) {
    int t = blockIdx.x * blockDim.x + threadIdx.x;   // 800k threads
    if (t < N_EDGES / 8) {
#pragma unroll
        for (int u = 0; u < 2; u++) {
            int4 s4 = ((const int4*)ei)[t * 2 + u];
            int4 dd = ((const int4*)(ei + N_EDGES))[t * 2 + u];
            int p0 = atomicAdd(&d_cnt[dd.x], 1);
            int p1 = atomicAdd(&d_cnt[dd.y], 1);
            int p2 = atomicAdd(&d_cnt[dd.z], 1);
            int p3 = atomicAdd(&d_cnt[dd.w], 1);
            if (p0 < SLOTS) d_csr[dd.x * SLOTS + p0] = s4.x;
            if (p1 < SLOTS) d_csr[dd.y * SLOTS + p1] = s4.y;
            if (p2 < SLOTS) d_csr[dd.z * SLOTS + p2] = s4.z;
            if (p3 < SLOTS) d_csr[dd.w * SLOTS + p3] = s4.w;
        }
    }
    if (t < N_NODES * 8) {
        int n = t >> 3, j = t & 7;
        d_xp[t] = (j < NF) ? x[n * NF + j] : 0.0f;
    }
}

// ---------------------------------------------------------------------------
// Layer 1 fused: 8 lanes per node; lane q owns output dims 4q..4q+3.
__global__ void __launch_bounds__(256)
gin1(const float* __restrict__ W1, const float* __restrict__ b1,
     const float* __restrict__ W2, const float* __restrict__ b2,
     const float* __restrict__ gamma, const float* __restrict__ beta,
     const float* __restrict__ mean, const float* __restrict__ var) {
    __shared__ float4 sW1[NF * 8], sW2[32 * 8];
    __shared__ float4 sB1[8], sB2[8], sSC[8], sSH[8];
    int tid = threadIdx.x;
    if (tid < NF * 8) sW1[tid] = ((const float4*)W1)[tid];
    for (int i = tid; i < 32 * 8; i += 256) sW2[i] = ((const float4*)W2)[i];
    if (tid < 32) {
        if (tid < 8) {
            sB1[tid] = ((const float4*)b1)[tid];
            sB2[tid] = ((const float4*)b2)[tid];
        }
        float sc = gamma[tid] * rsqrtf(var[tid] + 1e-5f);
        float sh = beta[tid] - mean[tid] * sc;
        ((float*)sSC)[tid] = sc;
        ((float*)sSH)[tid] = sh;
    }
    __syncthreads();

    int q = tid & 7;
    int n = (blockIdx.x * 256 + tid) >> 3;   // exact: 3125*32 = 100000

    int deg = d_cnt[n]; if (deg > SLOTS) deg = SLOTS;
    const int* row = d_csr + n * SLOTS;
    float zq = d_xp[n * 8 + q];
    float zb = 0.0f;
    int i = 0;
    for (; i + 2 <= deg; i += 2) {
        int s0 = row[i], s1 = row[i + 1];
        zq += d_xp[s0 * 8 + q];
        zb += d_xp[s1 * 8 + q];
    }
    if (i < deg) zq += d_xp[row[i] * 8 + q];
    zq += zb;

    float4 acc = sB1[q];
#pragma unroll
    for (int k = 0; k < NF; k++) {
        float zk = __shfl_sync(0xffffffffu, zq, k, 8);
        acc = fma4(zk, sW1[k * 8 + q], acc);
    }
    acc = relu4(acc);

    float4 o = sB2[q];
#pragma unroll
    for (int kg = 0; kg < 8; kg++) {
        float ax = __shfl_sync(0xffffffffu, acc.x, kg, 8);
        float ay = __shfl_sync(0xffffffffu, acc.y, kg, 8);
        float az = __shfl_sync(0xffffffffu, acc.z, kg, 8);
        float aw = __shfl_sync(0xffffffffu, acc.w, kg, 8);
        o = fma4(ax, sW2[(kg * 4 + 0) * 8 + q], o);
        o = fma4(ay, sW2[(kg * 4 + 1) * 8 + q], o);
        o = fma4(az, sW2[(kg * 4 + 2) * 8 + q], o);
        o = fma4(aw, sW2[(kg * 4 + 3) * 8 + q], o);
    }
    o = relu4(o);

    float4 sc = sSC[q], sh = sSH[q];
    float4 r;
    r.x = fmaf(o.x, sc.x, sh.x); r.y = fmaf(o.y, sc.y, sh.y);
    r.z = fmaf(o.z, sc.z, sh.z); r.w = fmaf(o.w, sc.w, sh.w);
    ((uint2*)d_hh0)[n * 8 + q] = pack_h4(r);
}

// Gather one node's aggregated z (fp32) — 8 loads in flight, 4 accumulators.
// Neighbor pairs are pre-summed in fp16 (HADD2) before fp32 accumulation:
// halves the cvt/FADD count; one extra fp16 rounding per neighbor value.
__device__ __forceinline__ float4 gather_node(const uint2* __restrict__ hin,
                                              int n, int q) {
    int deg = d_cnt[n]; if (deg > SLOTS) deg = SLOTS;
    const int4* row4 = reinterpret_cast<const int4*>(d_csr + n * SLOTS);

    float4 z0 = unpack_h4(hin[n * 8 + q]);
    float4 z1 = make_float4(0.f, 0.f, 0.f, 0.f);
    float4 z2 = make_float4(0.f, 0.f, 0.f, 0.f);
    float4 z3 = make_float4(0.f, 0.f, 0.f, 0.f);

    int i = 0;
    for (; i + 8 <= deg; i += 8) {
        int4 ia = row4[i >> 2];
        int4 ib = row4[(i >> 2) + 1];
        uint2 u0 = hin[ia.x * 8 + q];
        uint2 u1 = hin[ia.y * 8 + q];
        uint2 u2 = hin[ia.z * 8 + q];
        uint2 u3 = hin[ia.w * 8 + q];
        uint2 u4 = hin[ib.x * 8 + q];
        uint2 u5 = hin[ib.y * 8 + q];
        uint2 u6 = hin[ib.z * 8 + q];
        uint2 u7 = hin[ib.w * 8 + q];
        z0 = acc_h4(z0, hadd_u2(u0, u1));
        z1 = acc_h4(z1, hadd_u2(u2, u3));
        z2 = acc_h4(z2, hadd_u2(u4, u5));
        z3 = acc_h4(z3, hadd_u2(u6, u7));
    }
    if (i + 4 <= deg) {
        int4 ia = row4[i >> 2];
        uint2 u0 = hin[ia.x * 8 + q];
        uint2 u1 = hin[ia.y * 8 + q];
        uint2 u2 = hin[ia.z * 8 + q];
        uint2 u3 = hin[ia.w * 8 + q];
        z0 = acc_h4(z0, hadd_u2(u0, u1));
        z1 = acc_h4(z1, hadd_u2(u2, u3));
        i += 4;
    }
    const int* row = reinterpret_cast<const int*>(row4);
    for (; i < deg; i++) z0 = acc_h4(z0, hin[row[i] * 8 + q]);

    return add4(add4(z0, z1), add4(z2, z3));
}

// Layers 2..5: fp16 in, fp32 math. TWO nodes per thread; GEMVs use packed
// fma.rn.f32x2. NOTE: min-blocks=4 (natural ~59-64 regs). Forcing 5 causes
// spills (R11: +21us).
template <int POOL>
__global__ void __launch_bounds__(256, 4)
gin_layer(const uint2* __restrict__ hin, uint2* __restrict__ hout,
          const int* __restrict__ batch,
          const float* __restrict__ W1, const float* __restrict__ b1,
          const float* __restrict__ W2, const float* __restrict__ b2,
          const float* __restrict__ gamma, const float* __restrict__ beta,
          const float* __restrict__ mean, const float* __restrict__ var) {
    __shared__ ulonglong2 sW1[32 * 8], sW2[32 * 8];   // weights as f32x2 pairs
    __shared__ ulonglong2 sB1[8], sB2[8];
    __shared__ float4 sSC[8], sSH[8];
    int tid = threadIdx.x;
    for (int i = tid; i < 32 * 8; i += 256) {
        sW1[i] = ((const ulonglong2*)W1)[i];
        sW2[i] = ((const ulonglong2*)W2)[i];
    }
    if (tid < 32) {
        if (tid < 8) {
            sB1[tid] = ((const ulonglong2*)b1)[tid];
            sB2[tid] = ((const ulonglong2*)b2)[tid];
        }
        float sc = gamma[tid] * rsqrtf(var[tid] + 1e-5f);
        float sh = beta[tid] - mean[tid] * sc;
        ((float*)sSC)[tid] = sc;
        ((float*)sSH)[tid] = sh;
    }
    __syncthreads();

    int q = tid & 7;
    int grp = (blockIdx.x * 256 + tid) >> 3;   // 8-lane group id
    int nA = grp * 2;
    if (nA >= N_NODES) return;
    int nB = nA + 1;   // N_NODES even

    float4 zA = gather_node(hin, nA, q);
    float4 zB = gather_node(hin, nB, q);

    // GEMV1 (packed f32x2, weight LDS shared by both nodes)
    ulonglong2 b1v = sB1[q];
    unsigned long long aA01 = b1v.x, aA23 = b1v.y;
    unsigned long long aB01 = b1v.x, aB23 = b1v.y;
#pragma unroll
    for (int kg = 0; kg < 8; kg++) {
        ulonglong2 w0 = sW1[(kg * 4 + 0) * 8 + q];
        ulonglong2 w1 = sW1[(kg * 4 + 1) * 8 + q];
        ulonglong2 w2 = sW1[(kg * 4 + 2) * 8 + q];
        ulonglong2 w3 = sW1[(kg * 4 + 3) * 8 + q];
        unsigned long long sx = dup2(__shfl_sync(0xffffffffu, zA.x, kg, 8));
        unsigned long long sy = dup2(__shfl_sync(0xffffffffu, zA.y, kg, 8));
        unsigned long long sz = dup2(__shfl_sync(0xffffffffu, zA.z, kg, 8));
        unsigned long long sw = dup2(__shfl_sync(0xffffffffu, zA.w, kg, 8));
        aA01 = fma2(sx, w0.x, aA01); aA23 = fma2(sx, w0.y, aA23);
        aA01 = fma2(sy, w1.x, aA01); aA23 = fma2(sy, w1.y, aA23);
        aA01 = fma2(sz, w2.x, aA01); aA23 = fma2(sz, w2.y, aA23);
        aA01 = fma2(sw, w3.x, aA01); aA23 = fma2(sw, w3.y, aA23);
        unsigned long long tx = dup2(__shfl_sync(0xffffffffu, zB.x, kg, 8));
        unsigned long long ty = dup2(__shfl_sync(0xffffffffu, zB.y, kg, 8));
        unsigned long long tz = dup2(__shfl_sync(0xffffffffu, zB.z, kg, 8));
        unsigned long long tw = dup2(__shfl_sync(0xffffffffu, zB.w, kg, 8));
        aB01 = fma2(tx, w0.x, aB01); aB23 = fma2(tx, w0.y, aB23);
        aB01 = fma2(ty, w1.x, aB01); aB23 = fma2(ty, w1.y, aB23);
        aB01 = fma2(tz, w2.x, aB01); aB23 = fma2(tz, w2.y, aB23);
        aB01 = fma2(tw, w3.x, aB01); aB23 = fma2(tw, w3.y, aB23);
    }
    float2 aA0 = unpk2(aA01), aA1 = unpk2(aA23);
    float2 aB0 = unpk2(aB01), aB1 = unpk2(aB23);
    float4 aAf = make_float4(fmaxf(aA0.x, 0.f), fmaxf(aA0.y, 0.f),
                             fmaxf(aA1.x, 0.f), fmaxf(aA1.y, 0.f));
    float4 aBf = make_float4(fmaxf(aB0.x, 0.f), fmaxf(aB0.y, 0.f),
                             fmaxf(aB1.x, 0.f), fmaxf(aB1.y, 0.f));

    // GEMV2 (packed f32x2)
    ulonglong2 b2v = sB2[q];
    unsigned long long oA01 = b2v.x, oA23 = b2v.y;
    unsigned long long oB01 = b2v.x, oB23 = b2v.y;
#pragma unroll
    for (int kg = 0; kg < 8; kg++) {
        ulonglong2 w0 = sW2[(kg * 4 + 0) * 8 + q];
        ulonglong2 w1 = sW2[(kg * 4 + 1) * 8 + q];
        ulonglong2 w2 = sW2[(kg * 4 + 2) * 8 + q];
        ulonglong2 w3 = sW2[(kg * 4 + 3) * 8 + q];
        unsigned long long sx = dup2(__shfl_sync(0xffffffffu, aAf.x, kg, 8));
        unsigned long long sy = dup2(__shfl_sync(0xffffffffu, aAf.y, kg, 8));
        unsigned long long sz = dup2(__shfl_sync(0xffffffffu, aAf.z, kg, 8));
        unsigned long long sw = dup2(__shfl_sync(0xffffffffu, aAf.w, kg, 8));
        oA01 = fma2(sx, w0.x, oA01); oA23 = fma2(sx, w0.y, oA23);
        oA01 = fma2(sy, w1.x, oA01); oA23 = fma2(sy, w1.y, oA23);
        oA01 = fma2(sz, w2.x, oA01); oA23 = fma2(sz, w2.y, oA23);
        oA01 = fma2(sw, w3.x, oA01); oA23 = fma2(sw, w3.y, oA23);
        unsigned long long tx = dup2(__shfl_sync(0xffffffffu, aBf.x, kg, 8));
        unsigned long long ty = dup2(__shfl_sync(0xffffffffu, aBf.y, kg, 8));
        unsigned long long tz = dup2(__shfl_sync(0xffffffffu, aBf.z, kg, 8));
        unsigned long long tw = dup2(__shfl_sync(0xffffffffu, aBf.w, kg, 8));
        oB01 = fma2(tx, w0.x, oB01); oB23 = fma2(tx, w0.y, oB23);
        oB01 = fma2(ty, w1.x, oB01); oB23 = fma2(ty, w1.y, oB23);
        oB01 = fma2(tz, w2.x, oB01); oB23 = fma2(tz, w2.y, oB23);
        oB01 = fma2(tw, w3.x, oB01); oB23 = fma2(tw, w3.y, oB23);
    }
    float2 oA0 = unpk2(oA01), oA1 = unpk2(oA23);
    float2 oB0 = unpk2(oB01), oB1 = unpk2(oB23);
    float4 oAf = make_float4(fmaxf(oA0.x, 0.f), fmaxf(oA0.y, 0.f),
                             fmaxf(oA1.x, 0.f), fmaxf(oA1.y, 0.f));
    float4 oBf = make_float4(fmaxf(oB0.x, 0.f), fmaxf(oB0.y, 0.f),
                             fmaxf(oB1.x, 0.f), fmaxf(oB1.y, 0.f));

    float4 sc = sSC[q], sh = sSH[q];
    float4 rA, rB;
    rA.x = fmaf(oAf.x, sc.x, sh.x); rA.y = fmaf(oAf.y, sc.y, sh.y);
    rA.z = fmaf(oAf.z, sc.z, sh.z); rA.w = fmaf(oAf.w, sc.w, sh.w);
    rB.x = fmaf(oBf.x, sc.x, sh.x); rB.y = fmaf(oBf.y, sc.y, sh.y);
    rB.z = fmaf(oBf.z, sc.z, sh.z); rB.w = fmaf(oBf.w, sc.w, sh.w);

    if (POOL) {
        red_add_v4(&d_pool[batch[nA] * DIM + q * 4], rA);
        red_add_v4(&d_pool[batch[nB] * DIM + q * 4], rB);
    } else {
        hout[nA * 8 + q] = pack_h4(rA);
        hout[nB * 8 + q] = pack_h4(rB);
    }
}

// head: fc1 + relu + fc2 + log_softmax; one warp per graph
__global__ void head(const float* __restrict__ fc1W, const float* __restrict__ fc1b,
                     const float* __restrict__ fc2W, const float* __restrict__ fc2b,
                     float* __restrict__ out) {
    __shared__ float W1s[32 * 32], W2s[64], b1s[32], b2s[2];
    int tid = threadIdx.x;
    for (int i = tid; i < 32 * 32; i += blockDim.x) W1s[i] = fc1W[i];
    if (tid < 64) W2s[tid] = fc2W[tid];
    if (tid < 32) b1s[tid] = fc1b[tid];
    if (tid < 2)  b2s[tid] = fc2b[tid];
    __syncthreads();

    int warp = tid >> 5, j = tid & 31;
    int g = blockIdx.x * (blockDim.x >> 5) + warp;
    if (g >= N_GRAPHS) return;

    float gj = d_pool[g * DIM + j];
    float a = b1s[j];
#pragma unroll
    for (int k = 0; k < 32; k++)
        a = fmaf(__shfl_sync(0xffffffffu, gj, k), W1s[k * 32 + j], a);
    a = fmaxf(a, 0.0f);

    float p0 = a * W2s[j * 2 + 0];
    float p1 = a * W2s[j * 2 + 1];
#pragma unroll
    for (int off = 16; off > 0; off >>= 1) {
        p0 += __shfl_down_sync(0xffffffffu, p0, off);
        p1 += __shfl_down_sync(0xffffffffu, p1, off);
    }
    if (j == 0) {
        float z0 = p0 + b2s[0];
        float z1 = p1 + b2s[1];
        float m = fmaxf(z0, z1);
        float lse = m + logf(expf(z0 - m) + expf(z1 - m));
        out[g * 2 + 0] = z0 - lse;
        out[g * 2 + 1] = z1 - lse;
    }
}

// ---------------------------------------------------------------------------
extern "C" void kernel_launch(void* const* d_in, const int* in_sizes, int n_in,
                              void* d_out, int out_size) {
    const float* x        = (const float*)d_in[0];
    const int*   ei       = (const int*)d_in[1];
    const int*   batch    = (const int*)d_in[2];
    const float* conv1_W1 = (const float*)d_in[3];
    const float* conv1_b1 = (const float*)d_in[4];
    const float* conv1_W2 = (const float*)d_in[5];
    const float* conv1_b2 = (const float*)d_in[6];
    const float* convs_W1 = (const float*)d_in[7];
    const float* convs_b1 = (const float*)d_in[8];
    const float* convs_W2 = (const float*)d_in[9];
    const float* convs_b2 = (const float*)d_in[10];
    const float* bn_gamma = (const float*)d_in[11];
    const float* bn_beta  = (const float*)d_in[12];
    const float* bn_mean  = (const float*)d_in[13];
    const float* bn_var   = (const float*)d_in[14];
    const float* fc1_W    = (const float*)d_in[15];
    const float* fc1_b    = (const float*)d_in[16];
    const float* fc2_W    = (const float*)d_in[17];
    const float* fc2_b    = (const float*)d_in[18];
    float* out = (float*)d_out;

    zero_k<<<(N_NODES + 255) / 256, 256>>>();
    build<<<(N_NODES * 8 + 255) / 256, 256>>>(ei, x);

    unsigned* hA = nullptr; unsigned* hB = nullptr;
    cudaGetSymbolAddress((void**)&hA, d_hh0);
    cudaGetSymbolAddress((void**)&hB, d_hh1);

    const int NBLK1 = N_NODES * 8 / 256;            // 3125, exact (gin1)
    const int NBLK2 = (N_NODES * 4 + 255) / 256;    // 1563 (2 nodes/thread)

    // layer 1: xp (fp32) -> hh0 (fp16)
    gin1<<<NBLK1, 256>>>(conv1_W1, conv1_b1, conv1_W2, conv1_b2,
                         bn_gamma, bn_beta, bn_mean, bn_var);

    // layers 2..4: ping-pong hh0 -> hh1 -> hh0 -> hh1
    for (int i = 0; i < 3; i++) {
        const uint2* hin = (const uint2*)((i % 2 == 0) ? hA : hB);
        uint2* hout      = (uint2*)((i % 2 == 0) ? hB : hA);
        gin_layer<0><<<NBLK2, 256>>>(hin, hout, batch,
                                     convs_W1 + i * 32 * 32, convs_b1 + i * 32,
                                     convs_W2 + i * 32 * 32, convs_b2 + i * 32,
                                     bn_gamma + (i + 1) * 32, bn_beta + (i + 1) * 32,
                                     bn_mean + (i + 1) * 32,  bn_var + (i + 1) * 32);
    }

    // layer 5 (i=3): input hh1, output pooled (fp32) directly into d_pool
    gin_layer<1><<<NBLK2, 256>>>((const uint2*)hB, nullptr, batch,
                                 convs_W1 + 3 * 32 * 32, convs_b1 + 3 * 32,
                                 convs_W2 + 3 * 32 * 32, convs_b2 + 3 * 32,
                                 bn_gamma + 4 * 32, bn_beta + 4 * 32,
                                 bn_mean + 4 * 32,  bn_var + 4 * 32);

    head<<<(N_GRAPHS + 7) / 8, 256>>>(fc1_W, fc1_b, fc2_W, fc2_b, out);
}